// round 8
// baseline (speedup 1.0000x reference)
#include <cuda_runtime.h>
#include <cuda_fp16.h>

#define H 512
#define W 512
#define OW 128
#define OH 8
#define NPK 66            // even packs per row: halo cols 0..131
#define NT 256

#define CEH(a, b) { __half2 _t = __hmin2(a, b); (b) = __hmax2(a, b); (a) = _t; }

__device__ __forceinline__ int reflect_idx(int i) {
    i = abs(i);
    return (i >= H) ? (2 * H - 2 - i) : i;
}

// optimal 5-sort, 9 CE (elementwise on half2 lanes)
__device__ __forceinline__ void sort5h(__half2& x0, __half2& x1, __half2& x2,
                                       __half2& x3, __half2& x4) {
    CEH(x0, x1); CEH(x3, x4); CEH(x2, x4); CEH(x2, x3); CEH(x0, x3);
    CEH(x0, x2); CEH(x1, x4); CEH(x1, x3); CEH(x1, x2);
}

__device__ __forceinline__ __half2 u2h(unsigned u) { return *reinterpret_cast<__half2*>(&u); }
__device__ __forceinline__ unsigned h2u(__half2 h) { return *reinterpret_cast<unsigned*>(&h); }

// row statistics (validated R7): window w0..w4 per half2 lane
__device__ __forceinline__ void top2h(__half2 w0, __half2 w1, __half2 w2, __half2 w3,
                                      __half2 w4, __half2& A, __half2& B) {
    __half2 a = __hmin2(w0, w1), b = __hmax2(w0, w1);
    __half2 c = __hmin2(w2, w3), d = __hmax2(w2, w3);
    __half2 e = __hmax2(a, c);
    __half2 f = __hmin2(b, d), g = __hmax2(b, d);
    B = __hmax2(g, w4);
    __half2 h = __hmin2(g, w4);
    A = __hmax2(__hmax2(f, e), h);
}
__device__ __forceinline__ void top3h(__half2 w0, __half2 w1, __half2 w2, __half2 w3,
                                      __half2 w4, __half2& C, __half2& D, __half2& E) {
    __half2 a = __hmin2(w0, w1), b = __hmax2(w0, w1);
    __half2 c = __hmin2(w2, w3), d = __hmax2(w2, w3);
    __half2 e = __hmax2(a, c);
    __half2 f = __hmin2(b, d), g = __hmax2(b, d);
    __half2 p = __hmin2(e, f), q = __hmax2(e, f);
    E = __hmax2(g, w4);
    __half2 u = __hmin2(g, w4);
    D = __hmax2(q, u);
    __half2 v = __hmin2(q, u);
    C = __hmax2(p, v);
}
__device__ __forceinline__ void mid3h(__half2 x0, __half2 x1, __half2 x2, __half2 x3,
                                      __half2 x4, __half2& F, __half2& G, __half2& Hh) {
    CEH(x0, x1); CEH(x2, x3); CEH(x0, x2);
    x4 = __hmax2(x0, x4);
    CEH(x1, x4);
    x3 = __hmin2(x3, x4);
    CEH(x1, x2); CEH(x2, x3); CEH(x1, x2);
    F = x1; G = x2; Hh = x3;
}
__device__ __forceinline__ void bot3h(__half2 w0, __half2 w1, __half2 w2, __half2 w3,
                                      __half2 w4, __half2& I, __half2& J, __half2& K) {
    __half2 a = __hmin2(w0, w1), b = __hmax2(w0, w1);
    __half2 c = __hmin2(w2, w3), d = __hmax2(w2, w3);
    __half2 e = __hmin2(b, d);
    __half2 f = __hmin2(a, c), g = __hmax2(a, c);
    __half2 p = __hmin2(g, e), q = __hmax2(g, e);
    I = __hmin2(f, w4);
    __half2 u = __hmax2(f, w4);
    J = __hmin2(p, u);
    __half2 v = __hmax2(p, u);
    K = __hmin2(q, v);
}
__device__ __forceinline__ void bot2h(__half2 w0, __half2 w1, __half2 w2, __half2 w3,
                                      __half2 w4, __half2& L, __half2& M) {
    __half2 a = __hmin2(w0, w1), b = __hmax2(w0, w1);
    __half2 c = __hmin2(w2, w3), d = __hmax2(w2, w3);
    __half2 e = __hmin2(b, d);
    __half2 f = __hmin2(a, c), g = __hmax2(a, c);
    L = __hmin2(f, w4);
    __half2 h = __hmax2(f, w4);
    M = __hmin2(__hmin2(g, e), h);
}

// median (7th smallest) of 13 staircase candidates (validated R4-R7).
__device__ __forceinline__ __half2 sel13h(__half2 A, __half2 B, __half2 C, __half2 D,
                                          __half2 E, __half2 F, __half2 G, __half2 Hh,
                                          __half2 I, __half2 J, __half2 K, __half2 L,
                                          __half2 M) {
    CEH(A, C); CEH(E, Hh); CEH(C, E); CEH(B, D); CEH(B, C); CEH(D, E);
    CEH(F, I); CEH(K, M); CEH(I, K); CEH(G, J); CEH(G, I); CEH(J, K);
    __half2 s5 = __hmax2(__hmax2(__hmax2(__hmin2(A, M), __hmin2(B, K)),
                                 __hmax2(__hmin2(C, J), __hmin2(D, I))),
                         __hmax2(__hmin2(E, G), __hmin2(Hh, F)));
    __half2 s6 = __hmax2(__hmax2(__hmax2(A, __hmin2(B, M)),
                                 __hmax2(__hmin2(C, K), __hmin2(D, J))),
                         __hmax2(__hmax2(__hmin2(E, I), __hmin2(Hh, G)), F));
    return __hmin2(__hmax2(s5, L), s6);
}

__global__ __launch_bounds__(NT, 6) void median5x5_h4_kernel(
    const float* __restrict__ in, float* __restrict__ out) {
    // sorted even column-packs: pack p holds halo columns (2p, 2p+1) as half2
    __shared__ unsigned scolp[OH][5][NPK];

    const int bx = blockIdx.x * OW;
    const int by = blockIdx.y * OH;
    const int plane = blockIdx.z;
    const float* src = in + (size_t)plane * (H * W);

    const int tid = threadIdx.x;
    const bool interior = (bx >= 2) & (bx + OW + 2 <= W) & (by >= 2) & (by + OH + 2 <= H);

    // Phase B: sort each even column-pack over 5 vertically-adjacent rows.
    for (int k = tid; k < NPK * OH; k += NT) {
        int oy = k / NPK;
        int pp = k - oy * NPK;
        int sp = pp * 2;                        // even halo column
        __half2 v0, v1, v2, v3, v4;
        if (interior) {
            const float* p = src + (by + oy - 2) * W + (bx + sp - 2);   // 8B aligned
            v0 = __float22half2_rn(*(const float2*)(p));
            v1 = __float22half2_rn(*(const float2*)(p + W));
            v2 = __float22half2_rn(*(const float2*)(p + 2 * W));
            v3 = __float22half2_rn(*(const float2*)(p + 3 * W));
            v4 = __float22half2_rn(*(const float2*)(p + 4 * W));
        } else {
            int gx0 = reflect_idx(bx + sp - 2);
            int gx1 = reflect_idx(bx + sp - 1);
            int g0 = reflect_idx(by + oy - 2) * W;
            int g1 = reflect_idx(by + oy - 1) * W;
            int g2 = reflect_idx(by + oy + 0) * W;
            int g3 = reflect_idx(by + oy + 1) * W;
            int g4 = reflect_idx(by + oy + 2) * W;
            v0 = __floats2half2_rn(src[g0 + gx0], src[g0 + gx1]);
            v1 = __floats2half2_rn(src[g1 + gx0], src[g1 + gx1]);
            v2 = __floats2half2_rn(src[g2 + gx0], src[g2 + gx1]);
            v3 = __floats2half2_rn(src[g3 + gx0], src[g3 + gx1]);
            v4 = __floats2half2_rn(src[g4 + gx0], src[g4 + gx1]);
        }
        sort5h(v0, v1, v2, v3, v4);
        scolp[oy][0][pp] = h2u(v0);
        scolp[oy][1][pp] = h2u(v1);
        scolp[oy][2][pp] = h2u(v2);
        scolp[oy][3][pp] = h2u(v3);
        scolp[oy][4][pp] = h2u(v4);
    }
    __syncthreads();

    // Phase C: 4 adjacent pixels per thread = two independent half2 pairs.
    // Pair 0 covers pixels (4xp, 4xp+1); pair 1 covers (4xp+2, 4xp+3).
    const int oy = tid >> 5;
    const int xp = tid & 31;
    const int pbase = 2 * xp;

    // e_j = pack at halo col (4xp + 2j); odd window elements via PRMT.
#define ROWPACKS(r, w0, w1, w2, w3, w4, w5, w6)                       \
    __half2 w0, w1, w2, w3, w4, w5, w6;                               \
    {   unsigned _e0 = scolp[oy][r][pbase + 0];                       \
        unsigned _e1 = scolp[oy][r][pbase + 1];                       \
        unsigned _e2 = scolp[oy][r][pbase + 2];                       \
        unsigned _e3 = scolp[oy][r][pbase + 3];                       \
        w0 = u2h(_e0); w2 = u2h(_e1); w4 = u2h(_e2); w6 = u2h(_e3);   \
        w1 = u2h(__byte_perm(_e0, _e1, 0x5432));                      \
        w3 = u2h(__byte_perm(_e1, _e2, 0x5432));                      \
        w5 = u2h(__byte_perm(_e2, _e3, 0x5432)); }

    __half2 A0, B0, C0, D0, E0, F0, G0, H0, I0, J0, K0, L0, M0;
    __half2 A1, B1, C1, D1, E1, F1, G1, H1, I1, J1, K1, L1, M1;

    {   ROWPACKS(0, w0, w1, w2, w3, w4, w5, w6);
        top2h(w0, w1, w2, w3, w4, A0, B0);
        top2h(w2, w3, w4, w5, w6, A1, B1);
    }
    {   ROWPACKS(1, w0, w1, w2, w3, w4, w5, w6);
        top3h(w0, w1, w2, w3, w4, C0, D0, E0);
        top3h(w2, w3, w4, w5, w6, C1, D1, E1);
    }
    {   ROWPACKS(2, w0, w1, w2, w3, w4, w5, w6);
        mid3h(w0, w1, w2, w3, w4, F0, G0, H0);
        mid3h(w2, w3, w4, w5, w6, F1, G1, H1);
    }
    {   ROWPACKS(3, w0, w1, w2, w3, w4, w5, w6);
        bot3h(w0, w1, w2, w3, w4, I0, J0, K0);
        bot3h(w2, w3, w4, w5, w6, I1, J1, K1);
    }
    {   ROWPACKS(4, w0, w1, w2, w3, w4, w5, w6);
        bot2h(w0, w1, w2, w3, w4, L0, M0);
        bot2h(w2, w3, w4, w5, w6, L1, M1);
    }

    __half2 med0 = sel13h(A0, B0, C0, D0, E0, F0, G0, H0, I0, J0, K0, L0, M0);
    __half2 med1 = sel13h(A1, B1, C1, D1, E1, F1, G1, H1, I1, J1, K1, L1, M1);

    float4 o;
    o.x = __low2float(med0);
    o.y = __high2float(med0);
    o.z = __low2float(med1);
    o.w = __high2float(med1);
    *(float4*)(out + (size_t)plane * (H * W) + (by + oy) * W + (bx + 4 * xp)) = o;
#undef ROWPACKS
}

extern "C" void kernel_launch(void* const* d_in, const int* in_sizes, int n_in,
                              void* d_out, int out_size) {
    const float* img = (const float*)d_in[0];
    float* out = (float*)d_out;
    int planes = in_sizes[0] / (H * W);   // 4 * 3 = 12

    dim3 block(NT);
    dim3 grid(W / OW, H / OH, planes);
    median5x5_h4_kernel<<<grid, block>>>(img, out);
}